// round 10
// baseline (speedup 1.0000x reference)
#include <cuda_runtime.h>
#include <cstdint>

// Pink noise: 6-pole diagonal IIR + 1-sample delay, exact chunked scan.
// white[B, L] -> pink[B, L], L=65536, one block per channel.
//
// v7: v4's smem-transpose structure with DOUBLE-BUFFERED half-size tiles.
// SEG=8192, two 36.9KB tiles. stage(s+2) is issued at the end of iteration s
// (tile freed by writeout) and consumed at iteration s+2 -> a full iteration
// (~4000 cyc) of hide window instead of ~20 instructions. In-place pass B,
// padded stride-36 layout (conflict-free, no swizzle ALU), shuffle-based
// b6-carry, 4 barriers per segment.

#define NT      512
#define SEG     8192
#define NSEG    8
#define LROW    65536
#define NW      16
#define STRIDE  36                       // 32 data + 4 pad words per row
#define TILE_FLOATS (256 * STRIDE)       // 9216 floats = 36864 B per tile

typedef unsigned long long ull;

__device__ __forceinline__ ull pk2(float lo, float hi) {
    ull r; asm("mov.b64 %0, {%1, %2};" : "=l"(r) : "f"(lo), "f"(hi)); return r;
}
__device__ __forceinline__ void upk2(ull v, float& lo, float& hi) {
    asm("mov.b64 {%0, %1}, %2;" : "=f"(lo), "=f"(hi) : "l"(v));
}
__device__ __forceinline__ ull ffma2(ull a, ull b, ull c) {
    ull d; asm("fma.rn.f32x2 %0, %1, %2, %3;" : "=l"(d) : "l"(a), "l"(b), "l"(c)); return d;
}
__device__ __forceinline__ ull fmul2(ull a, ull b) {
    ull d; asm("mul.rn.f32x2 %0, %1, %2;" : "=l"(d) : "l"(a), "l"(b)); return d;
}

__device__ __forceinline__ void cpasync16(uint32_t dst, const void* src) {
    asm volatile("cp.async.cg.shared.global [%0], [%1], 16;" :: "r"(dst), "l"(src));
}
#define CP_COMMIT() asm volatile("cp.async.commit_group;" ::: "memory")
#define CP_WAIT0()  asm volatile("cp.async.wait_group 0;" ::: "memory")
#define CP_WAIT1()  asm volatile("cp.async.wait_group 1;" ::: "memory")

// Stage one 8192-sample segment (32KB) into a tile; fully coalesced.
// Rows of 32 samples, stride 36 (v4-proven conflict-free layout).
__device__ __forceinline__ void stage_seg(float* tile, const float* __restrict__ gseg,
                                          int tid) {
    uint32_t base = (uint32_t)__cvta_generic_to_shared(tile);
#pragma unroll
    for (int r = 0; r < 4; r++) {
        int f  = tid + r * NT;           // [0, 2048) float4 groups
        int j  = f >> 3;                 // row (8 float4 per 32-sample row)
        int i4 = (f & 7) * 4;
        cpasync16(base + (uint32_t)(j * STRIDE + i4) * 4u, gseg + (size_t)f * 4);
    }
}

__global__ void __launch_bounds__(NT, 2)
pink_kernel(const float* __restrict__ white, float* __restrict__ out) {
    extern __shared__ float smem[];
    float* T0 = smem;
    float* T1 = smem + TILE_FLOATS;
    __shared__ float warpT[NW][6];
    __shared__ float lastw[NW];

    const float A0 = 0.99886f, A1 = 0.99332f, A2 = 0.969f,
                A3 = 0.8665f,  A4 = 0.55f,    A5 = -0.7616f;
    const float OC0 = 0.11f * 0.0555179f, OC1 = 0.11f * 0.0750759f,
                OC2 = 0.11f * 0.153852f,  OC3 = 0.11f * 0.3104856f,
                OC4 = 0.11f * 0.5329522f, OC5 = 0.11f * -0.016898f;
    const float OB6 = 0.11f * 0.115926f, ODIR = 0.11f * 0.5362f;

    const int tid  = threadIdx.x;
    const int lane = tid & 31;
    const int wid  = tid >> 5;
    const float* wrow = white + (size_t)blockIdx.x * LROW;
    float*       orow = out   + (size_t)blockIdx.x * LROW;

    // Prologue: stage segments 0 and 1 (two commit groups).
    stage_seg(T0, wrow, tid);        CP_COMMIT();
    stage_seg(T1, wrow + SEG, tid);  CP_COMMIT();

    const ull A01 = pk2(A0, A1), A23 = pk2(A2, A3), A45 = pk2(A4, A5);
    const ull C01 = pk2(OC0, OC1), C23 = pk2(OC2, OC3), C45 = pk2(OC4, OC5);
    const ull ODB = pk2(ODIR, OB6);

    // Power tables (chunk = 16): m = a^16, mlane = m^lane, m32w = (m^32)^wid,
    // dseg = a^8192 = m^512.
    float m[6], mlane[6], m32w[6], dseg[6];
    {
        const float a[6] = {A0, A1, A2, A3, A4, A5};
#pragma unroll
        for (int i = 0; i < 6; i++) {
            float t = a[i];
#pragma unroll
            for (int s = 0; s < 4; s++) t *= t;        // a^16
            m[i] = t;
            float b = t, r = 1.f; int e = lane;
#pragma unroll
            for (int s = 0; s < 5; s++) { if (e & 1) r *= b; b *= b; e >>= 1; }
            mlane[i] = r;                              // b == m^32 now
            float b2 = b, r2 = 1.f; int e2 = wid;
#pragma unroll
            for (int s = 0; s < 4; s++) { if (e2 & 1) r2 *= b2; b2 *= b2; e2 >>= 1; }
            m32w[i] = r2;
            float d = m[i];
#pragma unroll
            for (int sq = 0; sq < 9; sq++) d *= d;     // m^512 = a^8192
            dseg[i] = d;
        }
    }

    float segState[6] = {0.f, 0.f, 0.f, 0.f, 0.f, 0.f};
    float w_carry = 0.f;

#pragma unroll 1
    for (int s = 0; s < NSEG; s++) {
        float* Wt = (s & 1) ? T1 : T0;
        // Oldest outstanding group must be this segment's stage.
        if (s < NSEG - 1) { CP_WAIT1(); } else { CP_WAIT0(); }
        __syncthreads();                               // B0: staged data visible

        // Thread t's 16-sample chunk: row t>>1, half (t&1).
        float* wr = Wt + (tid >> 1) * STRIDE + (tid & 1) * 16;

        // ---------------- Pass A: chunk particular state ----------------
        ull U01 = 0ull, U23 = 0ull, U45 = 0ull;
        float w15 = 0.f;
#pragma unroll
        for (int q = 0; q < 4; q++) {
            float4 wv = *reinterpret_cast<const float4*>(wr + 4 * q);
            float ws[4] = {wv.x, wv.y, wv.z, wv.w};
#pragma unroll
            for (int c = 0; c < 4; c++) {
                ull W = pk2(ws[c], ws[c]);
                U01 = ffma2(A01, U01, W);
                U23 = ffma2(A23, U23, W);
                U45 = ffma2(A45, U45, W);
            }
            if (q == 3) w15 = wv.w;
        }

        // ---------------- Block scan over 512 chunk states ----------------
        float pv[6];
        upk2(U01, pv[0], pv[1]); upk2(U23, pv[2], pv[3]); upk2(U45, pv[4], pv[5]);
        float mult[6];
#pragma unroll
        for (int i = 0; i < 6; i++) mult[i] = m[i];
#pragma unroll
        for (int o = 1; o < 32; o <<= 1) {
#pragma unroll
            for (int i = 0; i < 6; i++) {
                float up = __shfl_up_sync(0xffffffffu, pv[i], o);
                if (lane >= o) pv[i] = fmaf(mult[i], up, pv[i]);
                mult[i] *= mult[i];
            }
        }
        // mult == m^32
        float excl[6];
#pragma unroll
        for (int i = 0; i < 6; i++) {
            float e = __shfl_up_sync(0xffffffffu, pv[i], 1);
            excl[i] = (lane == 0) ? 0.f : e;
        }
        if (lane == 31) {
#pragma unroll
            for (int i = 0; i < 6; i++) warpT[wid][i] = pv[i];
            lastw[wid] = w15;
        }
        __syncthreads();                               // B1: warpT/lastw ready

        // Redundant all-warp combine over the 16 warp totals.
        float E[6], tot[6];
        {
            float t6[6], cm[6];
#pragma unroll
            for (int i = 0; i < 6; i++) {
                t6[i] = (lane < NW) ? warpT[lane][i] : 0.f;
                cm[i] = mult[i];                       // m^32
            }
#pragma unroll
            for (int o = 1; o < NW; o <<= 1) {
#pragma unroll
                for (int i = 0; i < 6; i++) {
                    float up = __shfl_up_sync(0xffffffffu, t6[i], o);
                    if (lane >= o) t6[i] = fmaf(cm[i], up, t6[i]);
                    cm[i] *= cm[i];
                }
            }
#pragma unroll
            for (int i = 0; i < 6; i++) {
                float pw = __shfl_sync(0xffffffffu, t6[i], (wid > 0) ? (wid - 1) : 0);
                if (wid == 0) pw = 0.f;
                tot[i] = __shfl_sync(0xffffffffu, t6[i], NW - 1);
                E[i] = fmaf(mlane[i], fmaf(m32w[i], segState[i], pw), excl[i]);
            }
        }

        // b6 delayed-white at the chunk boundary (shuffle + lastw, no tile read).
        float pwu = __shfl_up_sync(0xffffffffu, w15, 1);
        float prev_w;
        if (lane > 0)      prev_w = pwu;
        else if (wid > 0)  prev_w = lastw[wid - 1];
        else               prev_w = w_carry;
        w_carry = lastw[NW - 1];

#pragma unroll
        for (int i = 0; i < 6; i++)
            segState[i] = fmaf(dseg[i], segState[i], tot[i]);

        // ---------------- Pass B: exact recompute, in-place overwrite --------
        U01 = pk2(E[0], E[1]); U23 = pk2(E[2], E[3]); U45 = pk2(E[4], E[5]);
#pragma unroll
        for (int q = 0; q < 4; q++) {
            float4 wv = *reinterpret_cast<const float4*>(wr + 4 * q);
            float ws[4] = {wv.x, wv.y, wv.z, wv.w};
            float o4[4];
#pragma unroll
            for (int c = 0; c < 4; c++) {
                float w = ws[c];
                ull W = pk2(w, w);
                U01 = ffma2(A01, U01, W);
                U23 = ffma2(A23, U23, W);
                U45 = ffma2(A45, U45, W);
                ull P = ffma2(C01, U01, ffma2(C23, U23, fmul2(C45, U45)));
                ull T2 = ffma2(ODB, pk2(w, prev_w), P);
                float tlo, thi; upk2(T2, tlo, thi);
                o4[c] = tlo + thi;
                prev_w = w;
            }
            *reinterpret_cast<float4*>(wr + 4 * q) = make_float4(o4[0], o4[1], o4[2], o4[3]);
        }
        __syncthreads();                               // B2: outputs in tile

        // ---------------- Coalesced writeout ----------------
#pragma unroll
        for (int r = 0; r < 4; r++) {
            int f  = tid + r * NT;
            int j  = f >> 3;
            int i4 = (f & 7) * 4;
            float4 v = *reinterpret_cast<const float4*>(&Wt[j * STRIDE + i4]);
            *reinterpret_cast<float4*>(orow + (size_t)s * SEG + (size_t)f * 4) = v;
        }
        __syncthreads();                               // B3: tile reads done

        // Refill this tile for segment s+2 — consumed a full iteration later.
        if (s + 2 < NSEG) {
            stage_seg(Wt, wrow + (size_t)(s + 2) * SEG, tid);
            CP_COMMIT();
        }
    }
}

extern "C" void kernel_launch(void* const* d_in, const int* in_sizes, int n_in,
                              void* d_out, int out_size) {
    const float* white = (const float*)d_in[0];
    float* out = (float*)d_out;
    int B = out_size / LROW;

    size_t smem = (size_t)2 * TILE_FLOATS * sizeof(float);   // 73728 bytes
    cudaFuncSetAttribute(pink_kernel, cudaFuncAttributeMaxDynamicSharedMemorySize,
                         (int)smem);
    pink_kernel<<<B, NT, smem>>>(white, out);
}

// round 11
// speedup vs baseline: 1.6128x; 1.6128x over previous
#include <cuda_runtime.h>
#include <cstdint>

// Pink noise: 6-pole diagonal IIR + 1-sample delay, exact segment-resident scan.
// white[B, L] -> pink[B, L], L=65536, one block per channel.
//
// v8 = v4 (best: 39.6us) + hidden staging:
//  - Low half (rows 0..255) of each segment alternates between M-low and a
//    36KB scratch S: next segment's low half is cp.async'd right after the
//    scan, hidden under pass B + writeout.
//  - High half staged during writeout via thread-local read-then-overwrite
//    (same thread reads M[addr] into a register, then cp.asyncs the next
//    segment into the same addr - no barrier needed).
//  - wid0-only combine (MIO-friendly, as v4), shuffle-based prev_w
//    (6 -> 4 barriers per segment).

#define NT      512
#define SEG     16384
#define NSEG    4
#define LROW    65536
#define NW      16
#define STRIDE  36
#define M_FLOATS (512 * STRIDE)          // 18432 floats = 73728 B
#define S_FLOATS (256 * STRIDE)          //  9216 floats = 36864 B

typedef unsigned long long ull;

__device__ __forceinline__ ull pk2(float lo, float hi) {
    ull r; asm("mov.b64 %0, {%1, %2};" : "=l"(r) : "f"(lo), "f"(hi)); return r;
}
__device__ __forceinline__ void upk2(ull v, float& lo, float& hi) {
    asm("mov.b64 {%0, %1}, %2;" : "=f"(lo), "=f"(hi) : "l"(v));
}
__device__ __forceinline__ ull ffma2(ull a, ull b, ull c) {
    ull d; asm("fma.rn.f32x2 %0, %1, %2, %3;" : "=l"(d) : "l"(a), "l"(b), "l"(c)); return d;
}
__device__ __forceinline__ ull fmul2(ull a, ull b) {
    ull d; asm("mul.rn.f32x2 %0, %1, %2;" : "=l"(d) : "l"(a), "l"(b)); return d;
}

__device__ __forceinline__ void cpasync16(uint32_t dst, const void* src) {
    asm volatile("cp.async.cg.shared.global [%0], [%1], 16;" :: "r"(dst), "l"(src));
}
#define CP_COMMIT() asm volatile("cp.async.commit_group;" ::: "memory")
#define CP_WAIT0()  asm volatile("cp.async.wait_group 0;" ::: "memory")

// Stage the LOW half (rows 0..255, samples 0..8191) of a segment into dst.
__device__ __forceinline__ void stage_low(float* dst, const float* __restrict__ gseg,
                                          int tid) {
    uint32_t base = (uint32_t)__cvta_generic_to_shared(dst);
#pragma unroll
    for (int r = 0; r < 4; r++) {
        int f  = tid + r * NT;            // [0, 2048)
        int j  = f >> 3;                  // row 0..255
        int i4 = (f & 7) * 4;
        cpasync16(base + (uint32_t)(j * STRIDE + i4) * 4u, gseg + (size_t)f * 4);
    }
}

// Full-segment stage into M (prologue only).
__device__ __forceinline__ void stage_full(float* M, const float* __restrict__ gseg,
                                           int tid) {
    uint32_t base = (uint32_t)__cvta_generic_to_shared(M);
#pragma unroll
    for (int r = 0; r < 8; r++) {
        int f  = tid + r * NT;            // [0, 4096)
        int j  = f >> 3;
        int i4 = (f & 7) * 4;
        cpasync16(base + (uint32_t)(j * STRIDE + i4) * 4u, gseg + (size_t)f * 4);
    }
}

__global__ void __launch_bounds__(NT, 2)
pink_kernel(const float* __restrict__ white, float* __restrict__ out) {
    extern __shared__ float smem[];
    float* M = smem;                      // 512-row main tile
    float* S = smem + M_FLOATS;           // 256-row scratch (alternating low half)
    __shared__ float warpT[NW][6];
    __shared__ float warpW[NW][6];
    __shared__ float lastw[NW];

    const float A0 = 0.99886f, A1 = 0.99332f, A2 = 0.969f,
                A3 = 0.8665f,  A4 = 0.55f,    A5 = -0.7616f;
    const float OC0 = 0.11f * 0.0555179f, OC1 = 0.11f * 0.0750759f,
                OC2 = 0.11f * 0.153852f,  OC3 = 0.11f * 0.3104856f,
                OC4 = 0.11f * 0.5329522f, OC5 = 0.11f * -0.016898f;
    const float OB6 = 0.11f * 0.115926f, ODIR = 0.11f * 0.5362f;

    const int tid  = threadIdx.x;
    const int lane = tid & 31;
    const int wid  = tid >> 5;
    const float* wrow = white + (size_t)blockIdx.x * LROW;
    float*       orow = out   + (size_t)blockIdx.x * LROW;

    // Prologue: full segment 0 into M.
    stage_full(M, wrow, tid);
    CP_COMMIT();

    const ull A01 = pk2(A0, A1), A23 = pk2(A2, A3), A45 = pk2(A4, A5);
    const ull C01 = pk2(OC0, OC1), C23 = pk2(OC2, OC3), C45 = pk2(OC4, OC5);
    const ull ODB = pk2(ODIR, OB6);

    // m = a^32; mlane = m^lane; m32w = (m^32)^wid; d512 = m^512 = a^16384.
    float m[6], mlane[6], m32w[6], d512[6];
    {
        const float a[6] = {A0, A1, A2, A3, A4, A5};
#pragma unroll
        for (int i = 0; i < 6; i++) {
            float t = a[i];
#pragma unroll
            for (int s = 0; s < 5; s++) t *= t;
            m[i] = t;                                  // a^32
            float b = t, r = 1.f; int e = lane;
#pragma unroll
            for (int s = 0; s < 5; s++) { if (e & 1) r *= b; b *= b; e >>= 1; }
            mlane[i] = r;                              // b == m^32 now
            float b2 = b, r2 = 1.f; int e2 = wid;
#pragma unroll
            for (int s = 0; s < 4; s++) { if (e2 & 1) r2 *= b2; b2 *= b2; e2 >>= 1; }
            m32w[i] = r2;
            float d = m[i];
#pragma unroll
            for (int sq = 0; sq < 9; sq++) d *= d;
            d512[i] = d;
        }
    }

    float segState[6] = {0.f, 0.f, 0.f, 0.f, 0.f, 0.f};
    float w_carry = 0.f;

#pragma unroll 1
    for (int s = 0; s < NSEG; s++) {
        CP_WAIT0();
        __syncthreads();                               // B0: segment visible

        // Low half alternates: even s -> M-low, odd s -> S. High always M.
        float* lowb = (s & 1) ? S : M;
        float* wr = ((tid < 256) ? lowb : M) + tid * STRIDE;

        // ---------------- Pass A: chunk particular state ----------------
        ull U01 = 0ull, U23 = 0ull, U45 = 0ull;
        float w31 = 0.f;
#pragma unroll
        for (int q = 0; q < 8; q++) {
            float4 wv = *reinterpret_cast<const float4*>(wr + 4 * q);
            float ws[4] = {wv.x, wv.y, wv.z, wv.w};
#pragma unroll
            for (int c = 0; c < 4; c++) {
                ull W = pk2(ws[c], ws[c]);
                U01 = ffma2(A01, U01, W);
                U23 = ffma2(A23, U23, W);
                U45 = ffma2(A45, U45, W);
            }
            if (q == 7) w31 = wv.w;
        }

        // ---------------- Block scan ----------------
        float pv[6];
        upk2(U01, pv[0], pv[1]); upk2(U23, pv[2], pv[3]); upk2(U45, pv[4], pv[5]);
        float mult[6];
#pragma unroll
        for (int i = 0; i < 6; i++) mult[i] = m[i];
#pragma unroll
        for (int o = 1; o < 32; o <<= 1) {
#pragma unroll
            for (int i = 0; i < 6; i++) {
                float up = __shfl_up_sync(0xffffffffu, pv[i], o);
                if (lane >= o) pv[i] = fmaf(mult[i], up, pv[i]);
                mult[i] *= mult[i];
            }
        }
        // mult == m^32
        float excl[6];
#pragma unroll
        for (int i = 0; i < 6; i++) {
            float e = __shfl_up_sync(0xffffffffu, pv[i], 1);
            excl[i] = (lane == 0) ? 0.f : e;
        }
        if (lane == 31) {
#pragma unroll
            for (int i = 0; i < 6; i++) warpT[wid][i] = pv[i];
            lastw[wid] = w31;
        }
        __syncthreads();                               // B1: warpT ready

        if (wid == 0) {                                // wid0-only combine (MIO-cheap)
            float t6[6], cm[6];
#pragma unroll
            for (int i = 0; i < 6; i++) {
                t6[i] = (lane < NW) ? warpT[lane][i] : 0.f;
                cm[i] = mult[i];                       // m^32
            }
#pragma unroll
            for (int o = 1; o < NW; o <<= 1) {
#pragma unroll
                for (int i = 0; i < 6; i++) {
                    float up = __shfl_up_sync(0xffffffffu, t6[i], o);
                    if (lane >= o) t6[i] = fmaf(cm[i], up, t6[i]);
                    cm[i] *= cm[i];
                }
            }
            if (lane < NW) {
#pragma unroll
                for (int i = 0; i < 6; i++) warpW[lane][i] = t6[i];
            }
        }
        __syncthreads();                               // B2: warpW ready

        float E[6];
#pragma unroll
        for (int i = 0; i < 6; i++) {
            float pw = (wid == 0) ? 0.f : warpW[wid - 1][i];
            E[i] = fmaf(mlane[i], fmaf(m32w[i], segState[i], pw), excl[i]);
        }

        // b6 delayed-white at chunk boundary (shuffle + lastw).
        float pwu = __shfl_up_sync(0xffffffffu, w31, 1);
        float prev_w;
        if (lane > 0)      prev_w = pwu;
        else if (wid > 0)  prev_w = lastw[wid - 1];
        else               prev_w = w_carry;
        w_carry = lastw[NW - 1];

#pragma unroll
        for (int i = 0; i < 6; i++)
            segState[i] = fmaf(d512[i], segState[i], warpW[NW - 1][i]);

        // Stage next segment's LOW half into the other low buffer now:
        // hidden under pass B + writeout (~2000+ cycles).
        if (s + 1 < NSEG) {
            float* nlow = (s & 1) ? M : S;
            stage_low(nlow, wrow + (size_t)(s + 1) * SEG, tid);
            CP_COMMIT();
        }

        // ---------------- Pass B: exact recompute, in-place ----------------
        U01 = pk2(E[0], E[1]); U23 = pk2(E[2], E[3]); U45 = pk2(E[4], E[5]);
#pragma unroll
        for (int q = 0; q < 8; q++) {
            float4 wv = *reinterpret_cast<const float4*>(wr + 4 * q);
            float ws[4] = {wv.x, wv.y, wv.z, wv.w};
            float o4[4];
#pragma unroll
            for (int c = 0; c < 4; c++) {
                float w = ws[c];
                ull W = pk2(w, w);
                U01 = ffma2(A01, U01, W);
                U23 = ffma2(A23, U23, W);
                U45 = ffma2(A45, U45, W);
                ull P = ffma2(C01, U01, ffma2(C23, U23, fmul2(C45, U45)));
                ull T2 = ffma2(ODB, pk2(w, prev_w), P);
                float tlo, thi; upk2(T2, tlo, thi);
                o4[c] = tlo + thi;
                prev_w = w;
            }
            *reinterpret_cast<float4*>(wr + 4 * q) = make_float4(o4[0], o4[1], o4[2], o4[3]);
        }
        __syncthreads();                               // B3: outputs ready

        // ---------------- Writeout ----------------
        const float* gnext = wrow + (size_t)(s + 1) * SEG;
        uint32_t mbase = (uint32_t)__cvta_generic_to_shared(M);
        // Low rows 0..255 from the low buffer.
#pragma unroll
        for (int r = 0; r < 4; r++) {
            int f  = tid + r * NT;                     // [0, 2048)
            int j  = f >> 3;
            int i4 = (f & 7) * 4;
            float4 v = *reinterpret_cast<const float4*>(&lowb[j * STRIDE + i4]);
            *reinterpret_cast<float4*>(orow + (size_t)s * SEG + (size_t)f * 4) = v;
        }
        // High rows 256..511 from M, with thread-local overwrite staging of the
        // next segment's high half into the SAME addresses just read.
#pragma unroll
        for (int r = 4; r < 8; r++) {
            int f  = tid + r * NT;                     // [2048, 4096)
            int j  = f >> 3;
            int i4 = (f & 7) * 4;
            float4 v = *reinterpret_cast<const float4*>(&M[j * STRIDE + i4]);
            *reinterpret_cast<float4*>(orow + (size_t)s * SEG + (size_t)f * 4) = v;
            if (s + 1 < NSEG)
                cpasync16(mbase + (uint32_t)(j * STRIDE + i4) * 4u,
                          gnext + (size_t)f * 4);
        }
        if (s + 1 < NSEG) CP_COMMIT();
        // no end barrier: next iteration's CP_WAIT0 + B0 provide the ordering
    }
}

extern "C" void kernel_launch(void* const* d_in, const int* in_sizes, int n_in,
                              void* d_out, int out_size) {
    const float* white = (const float*)d_in[0];
    float* out = (float*)d_out;
    int B = out_size / LROW;

    size_t smem = (size_t)(M_FLOATS + S_FLOATS) * sizeof(float);  // 110592 bytes
    cudaFuncSetAttribute(pink_kernel, cudaFuncAttributeMaxDynamicSharedMemorySize,
                         (int)smem);
    pink_kernel<<<B, NT, smem>>>(white, out);
}